// round 1
// baseline (speedup 1.0000x reference)
#include <cuda_runtime.h>
#include <math.h>

#define BB 8
#define NN 2048
#define MM 2048
#define FEPS 1e-12f

// ---------------- scratch (device globals; no allocs allowed) ----------------
__device__ float g_invt[BB];                 // 1/(4*alpha) per batch
__device__ float g_minsq[BB][4][NN];         // alpha partial mins (4 m-chunks)
__device__ float g_colpart[BB][4][MM];       // colsum partials (4 n-chunks)
__device__ float g_invC[BB][MM];             // 1/colsum
__device__ float g_part6[BB][4][6][NN];      // main-pass partials: Rn,S2,G,c0,c1,c2
__device__ float g_gamma[BB][NN];

__device__ __forceinline__ float fsqrt_a(float x) {
    float r; asm("sqrt.approx.f32 %0, %1;" : "=f"(r) : "f"(x)); return r;
}

// ---------------- K1: alpha partial min over m-chunks ----------------
// grid (8 ntile, 4 mchunk, 8 b), 256 threads. min over squared distances
// (sqrt deferred to the combine step — monotone).
__global__ void k_alpha_part(const float* __restrict__ src) {
    int b = blockIdx.z, nt = blockIdx.x, mc = blockIdx.y, tid = threadIdx.x;
    int n = nt * 256 + tid;
    const float* S = src + b * 3 * NN;
    __shared__ float sx[512], sy[512], sz[512], sq2[512];
    float x = S[n], y = S[NN + n], z = S[2 * NN + n];
    float pn = x * x + y * y + z * z;
    int mb = mc * 512;
    for (int j = tid; j < 512; j += 256) {
        float a = S[mb + j], c = S[NN + mb + j], d = S[2 * NN + mb + j];
        sx[j] = a; sy[j] = c; sz[j] = d; sq2[j] = a * a + c * c + d * d;
    }
    __syncthreads();
    float mn = 1e30f;
#pragma unroll 8
    for (int j = 0; j < 512; j++) {
        float sq = pn + sq2[j] - 2.0f * (x * sx[j] + y * sy[j] + z * sz[j]);
        if (mb + j == n) sq = 1e30f;   // exclude diagonal
        mn = fminf(mn, sq);
    }
    g_minsq[b][mc][n] = mn;
}

// ---------------- K2: combine alpha -> invt ----------------
__global__ void k_alpha_comb() {
    int b = blockIdx.x, tid = threadIdx.x;
    __shared__ float red[256];
    float s = 0.0f;
    for (int n = tid; n < NN; n += 256) {
        float mn = fminf(fminf(g_minsq[b][0][n], g_minsq[b][1][n]),
                         fminf(g_minsq[b][2][n], g_minsq[b][3][n]));
        s += fsqrt_a(fmaxf(mn, FEPS));
    }
    red[tid] = s; __syncthreads();
    for (int st = 128; st > 0; st >>= 1) {
        if (tid < st) red[tid] += red[tid + st];
        __syncthreads();
    }
    if (tid == 0) {
        float alpha = red[0] * (1.0f / (float)NN);
        g_invt[b] = 1.0f / (4.0f * alpha);
    }
}

// ---------------- K3: column softmax denominators (partials) ----------------
// grid (8 mtile, 4 nchunk, 8 b), 256 threads; thread owns one m, loops 512 n.
__global__ void k_colsum_part(const float* __restrict__ src, const float* __restrict__ tgt) {
    int b = blockIdx.z, mt = blockIdx.x, nc = blockIdx.y, tid = threadIdx.x;
    int m = mt * 256 + tid;
    const float* S = src + b * 3 * NN;
    const float* T = tgt + b * 3 * MM;
    __shared__ float sx[512], sy[512], sz[512], sq2[512];
    float x = T[m], y = T[MM + m], z = T[2 * MM + m];
    float pn = x * x + y * y + z * z;
    float invt = g_invt[b];
    int nb = nc * 512;
    for (int j = tid; j < 512; j += 256) {
        float a = S[nb + j], c = S[NN + nb + j], d = S[2 * NN + nb + j];
        sx[j] = a; sy[j] = c; sz[j] = d; sq2[j] = a * a + c * c + d * d;
    }
    __syncthreads();
    float s = 0.0f;
#pragma unroll 8
    for (int j = 0; j < 512; j++) {
        float sq = pn + sq2[j] - 2.0f * (x * sx[j] + y * sy[j] + z * sz[j]);
        float d = fsqrt_a(fmaxf(sq, FEPS));
        s += __expf(-d * invt);
    }
    g_colpart[b][nc][m] = s;
}

// ---------------- K4: combine colsums -> invC ----------------
__global__ void k_colsum_comb() {
    int idx = blockIdx.x * 256 + threadIdx.x;   // 64*256 = 16384
    int b = idx >> 11, m = idx & (MM - 1);
    float s = g_colpart[b][0][m] + g_colpart[b][1][m] + g_colpart[b][2][m] + g_colpart[b][3][m];
    g_invC[b][m] = 1.0f / s;
}

// ---------------- K5: main pass partials ----------------
// grid (8 ntile, 4 mchunk, 8 b), 256 threads; thread owns one n, loops 512 m.
__global__ void k_main_part(const float* __restrict__ src, const float* __restrict__ tgt,
                            const int* __restrict__ iter) {
    int b = blockIdx.z, nt = blockIdx.x, mc = blockIdx.y, tid = threadIdx.x;
    int n = nt * 256 + tid;
    const float* S = src + b * 3 * NN;
    const float* T = tgt + b * 3 * MM;
    __shared__ float tx[512], ty[512], tz[512], tq[512], tic[512];
    float x = S[n], y = S[NN + n], z = S[2 * NN + n];
    float pn = x * x + y * y + z * z;
    float invt = g_invt[b];
    float invT = exp2f((float)(*iter - 1));   // 1/T = 2^(iter-1)
    int mb = mc * 512;
    for (int j = tid; j < 512; j += 256) {
        float a = T[mb + j], c = T[MM + mb + j], d = T[2 * MM + mb + j];
        tx[j] = a; ty[j] = c; tz[j] = d; tq[j] = a * a + c * c + d * d;
        tic[j] = g_invC[b][mb + j];
    }
    __syncthreads();
    float Rn = 0.f, S2 = 0.f, G = 0.f, c0 = 0.f, c1 = 0.f, c2 = 0.f;
#pragma unroll 4
    for (int j = 0; j < 512; j++) {
        float sq = pn + tq[j] - 2.0f * (x * tx[j] + y * ty[j] + z * tz[j]);
        float d = fsqrt_a(fmaxf(sq, FEPS));
        float e = __expf(-d * invt);        // row/col softmax numerator
        float w = e * e * tic[j];           // e^2 / C_m
        Rn += e;
        S2 += w;
        G  += w * __expf(-d * invT);
        c0 = fmaf(w, tx[j], c0);
        c1 = fmaf(w, ty[j], c1);
        c2 = fmaf(w, tz[j], c2);
    }
    g_part6[b][mc][0][n] = Rn;
    g_part6[b][mc][1][n] = S2;
    g_part6[b][mc][2][n] = G;
    g_part6[b][mc][3][n] = c0;
    g_part6[b][mc][4][n] = c1;
    g_part6[b][mc][5][n] = c2;
}

// ---------------- K6: finalize per-n: gamma + src_corr ----------------
// out layout: [0,72) R, [72,96) t, [96, 96+B*3*N) src_corr
__global__ void k_finalize(float* __restrict__ out) {
    int idx = blockIdx.x * 256 + threadIdx.x;   // 16384
    int b = idx >> 11, n = idx & (NN - 1);
    float Rn = 0.f, S2 = 0.f, G = 0.f, c0 = 0.f, c1 = 0.f, c2 = 0.f;
#pragma unroll
    for (int mc = 0; mc < 4; mc++) {
        Rn += g_part6[b][mc][0][n];
        S2 += g_part6[b][mc][1][n];
        G  += g_part6[b][mc][2][n];
        c0 += g_part6[b][mc][3][n];
        c1 += g_part6[b][mc][4][n];
        c2 += g_part6[b][mc][5][n];
    }
    float gamma = G / Rn;
    float invden = 1.0f / (S2 + FEPS * Rn);   // scores_norm denominator * Rn
    g_gamma[b][n] = gamma;
    float* corr = out + 96;
    corr[(b * 3 + 0) * NN + n] = c0 * invden;
    corr[(b * 3 + 1) * NN + n] = c1 * invden;
    corr[(b * 3 + 2) * NN + n] = c2 * invden;
}

// ---------------- 3x3 Procrustes SVD (double, one thread) ----------------
__device__ void svd3_kabsch(const double H[3][3], double R[3][3]) {
    // Jacobi eigen on A = H^T H
    double A[3][3];
    for (int i = 0; i < 3; i++)
        for (int j = 0; j < 3; j++) {
            double s = 0;
            for (int k = 0; k < 3; k++) s += H[k][i] * H[k][j];
            A[i][j] = s;
        }
    double V[3][3] = {{1,0,0},{0,1,0},{0,0,1}};
    const int PQ[3][2] = {{0,1},{0,2},{1,2}};
    for (int sweep = 0; sweep < 30; sweep++) {
        double off = fabs(A[0][1]) + fabs(A[0][2]) + fabs(A[1][2]);
        if (off < 1e-30) break;
        for (int r = 0; r < 3; r++) {
            int p = PQ[r][0], q = PQ[r][1];
            double apq = A[p][q];
            if (fabs(apq) < 1e-300) continue;
            double theta = (A[q][q] - A[p][p]) / (2.0 * apq);
            double t = ((theta >= 0.0) ? 1.0 : -1.0) / (fabs(theta) + sqrt(1.0 + theta * theta));
            double c = 1.0 / sqrt(1.0 + t * t), s = t * c;
            for (int k = 0; k < 3; k++) {
                double akp = A[k][p], akq = A[k][q];
                A[k][p] = c * akp - s * akq;
                A[k][q] = s * akp + c * akq;
            }
            for (int k = 0; k < 3; k++) {
                double apk = A[p][k], aqk = A[q][k];
                A[p][k] = c * apk - s * aqk;
                A[q][k] = s * apk + c * aqk;
            }
            for (int k = 0; k < 3; k++) {
                double vkp = V[k][p], vkq = V[k][q];
                V[k][p] = c * vkp - s * vkq;
                V[k][q] = s * vkp + c * vkq;
            }
        }
    }
    // sort eigenvalues descending
    int idx[3] = {0, 1, 2};
    double lam[3] = {A[0][0], A[1][1], A[2][2]};
    for (int i = 0; i < 2; i++)
        for (int j = i + 1; j < 3; j++)
            if (lam[idx[j]] > lam[idx[i]]) { int t = idx[i]; idx[i] = idx[j]; idx[j] = t; }
    double U[3][3], Vs[3][3];  // columns
    for (int i = 0; i < 3; i++) {
        int id = idx[i];
        double v0 = V[0][id], v1 = V[1][id], v2 = V[2][id];
        double u0 = H[0][0]*v0 + H[0][1]*v1 + H[0][2]*v2;
        double u1 = H[1][0]*v0 + H[1][1]*v1 + H[1][2]*v2;
        double u2 = H[2][0]*v0 + H[2][1]*v1 + H[2][2]*v2;
        double sig = sqrt(u0*u0 + u1*u1 + u2*u2);
        sig = (sig > 1e-300) ? sig : 1e-300;
        U[0][i] = u0 / sig; U[1][i] = u1 / sig; U[2][i] = u2 / sig;
        Vs[0][i] = v0; Vs[1][i] = v1; Vs[2][i] = v2;
    }
    double detH = H[0][0]*(H[1][1]*H[2][2] - H[1][2]*H[2][1])
                - H[0][1]*(H[1][0]*H[2][2] - H[1][2]*H[2][0])
                + H[0][2]*(H[1][0]*H[2][1] - H[1][1]*H[2][0]);
    double flip = (detH < 0.0) ? -1.0 : 1.0;   // sign(det(V U^T))
    Vs[0][2] *= flip; Vs[1][2] *= flip; Vs[2][2] *= flip;
    for (int r = 0; r < 3; r++)
        for (int c = 0; c < 3; c++)
            R[r][c] = Vs[r][0]*U[c][0] + Vs[r][1]*U[c][1] + Vs[r][2]*U[c][2];
}

// ---------------- K7: per-batch reduce + SVD + R,t ----------------
__global__ void k_reduce_svd(const float* __restrict__ src, float* __restrict__ out) {
    int b = blockIdx.x, tid = threadIdx.x;
    const float* S = src + b * 3 * NN;
    const float* C = out + 96 + b * 3 * NN;
    float acc[16];
#pragma unroll
    for (int k = 0; k < 16; k++) acc[k] = 0.0f;
    for (int n = tid; n < NN; n += 256) {
        float g = g_gamma[b][n];
        float sx = S[n], sy = S[NN + n], sz = S[2 * NN + n];
        float cx = C[n], cy = C[NN + n], cz = C[2 * NN + n];
        acc[0] += g;
        acc[1] += g * sx;  acc[2] += g * sy;  acc[3] += g * sz;
        acc[4] += g * cx;  acc[5] += g * cy;  acc[6] += g * cz;
        acc[7]  += g * sx * cx; acc[8]  += g * sx * cy; acc[9]  += g * sx * cz;
        acc[10] += g * sy * cx; acc[11] += g * sy * cy; acc[12] += g * sy * cz;
        acc[13] += g * sz * cx; acc[14] += g * sz * cy; acc[15] += g * sz * cz;
    }
    __shared__ float red[256];
    __shared__ float tot[16];
    for (int k = 0; k < 16; k++) {
        red[tid] = acc[k]; __syncthreads();
        for (int st = 128; st > 0; st >>= 1) {
            if (tid < st) red[tid] += red[tid + st];
            __syncthreads();
        }
        if (tid == 0) tot[k] = red[0];
        __syncthreads();
    }
    if (tid == 0) {
        double g1 = tot[0];
        double Ss[3] = {tot[1], tot[2], tot[3]};
        double Sc[3] = {tot[4], tot[5], tot[6]};
        double Mm[3][3] = {{tot[7], tot[8], tot[9]},
                           {tot[10], tot[11], tot[12]},
                           {tot[13], tot[14], tot[15]}};
        double gsum = g1 + 1e-12;
        double sm[3], cm[3];
        for (int d = 0; d < 3; d++) { sm[d] = Ss[d] / gsum; cm[d] = Sc[d] / gsum; }
        double H[3][3];
        for (int r = 0; r < 3; r++)
            for (int c = 0; c < 3; c++)
                H[r][c] = Mm[r][c] - sm[r] * Sc[c] - cm[c] * Ss[r] + sm[r] * cm[c] * g1;
        H[0][0] += 1e-12; H[1][1] += 2e-12; H[2][2] += 3e-12;
        double R[3][3];
        svd3_kabsch(H, R);
        for (int r = 0; r < 3; r++)
            for (int c = 0; c < 3; c++)
                out[b * 9 + r * 3 + c] = (float)R[r][c];
        for (int d = 0; d < 3; d++)
            out[72 + b * 3 + d] =
                (float)(-(R[d][0] * sm[0] + R[d][1] * sm[1] + R[d][2] * sm[2]) + cm[d]);
    }
}

// ---------------- launch ----------------
extern "C" void kernel_launch(void* const* d_in, const int* in_sizes, int n_in,
                              void* d_out, int out_size) {
    const float* src = (const float*)d_in[0];
    const float* tgt = (const float*)d_in[1];
    const int* iter = (const int*)d_in[2];
    float* out = (float*)d_out;

    k_alpha_part<<<dim3(8, 4, 8), 256>>>(src);
    k_alpha_comb<<<8, 256>>>();
    k_colsum_part<<<dim3(8, 4, 8), 256>>>(src, tgt);
    k_colsum_comb<<<64, 256>>>();
    k_main_part<<<dim3(8, 4, 8), 256>>>(src, tgt, iter);
    k_finalize<<<64, 256>>>(out);
    k_reduce_svd<<<8, 256>>>(src, out);
}

// round 2
// speedup vs baseline: 1.1799x; 1.1799x over previous
#include <cuda_runtime.h>
#include <math.h>

#define BB 8
#define NN 2048
#define MM 2048
#define FEPS 1e-12f
#define L2E 1.4426950408889634f

// ---------------- scratch (device globals; no allocs allowed) ----------------
__device__ float g_invt[BB];                 // 1/(4*alpha) per batch
__device__ float g_minsq[BB][8][NN];         // alpha partial mins (8 m-chunks)
__device__ float g_colpart[BB][8][MM];       // colsum partials (8 n-chunks)
__device__ float g_part6[BB][8][6][NN];      // main-pass partials: Rn,S2,G,c0,c1,c2

__device__ __forceinline__ float fsqrt_a(float x) {
    float r; asm("sqrt.approx.f32 %0, %1;" : "=f"(r) : "f"(x)); return r;
}
__device__ __forceinline__ float frcp_a(float x) {
    float r; asm("rcp.approx.f32 %0, %1;" : "=f"(r) : "f"(x)); return r;
}

// ---------------- K1: alpha partial min over m-chunks ----------------
// grid (4 ntile, 8 mchunk, 8 b), 256 threads; thread owns n0 and n0+256 (512 n/block),
// m-chunk of 256 in shared (float4 broadcast tile).
__global__ void k_alpha_part(const float* __restrict__ src) {
    int b = blockIdx.z, nt = blockIdx.x, mc = blockIdx.y, tid = threadIdx.x;
    int n0 = nt * 512 + tid, n1 = n0 + 256;
    int mb = mc * 256;
    const float* S = src + b * 3 * NN;
    __shared__ float4 tile[256];
    {
        float a = S[mb + tid], c = S[NN + mb + tid], d = S[2 * NN + mb + tid];
        tile[tid] = make_float4(a, c, d, a * a + c * c + d * d);
    }
    float x0 = S[n0], y0 = S[NN + n0], z0 = S[2 * NN + n0];
    float x1 = S[n1], y1 = S[NN + n1], z1 = S[2 * NN + n1];
    float pn0 = x0 * x0 + y0 * y0 + z0 * z0;
    float pn1 = x1 * x1 + y1 * y1 + z1 * z1;
    __syncthreads();
    float mn0 = 1e30f, mn1 = 1e30f;
#pragma unroll 8
    for (int j = 0; j < 256; j++) {
        float4 p = tile[j];
        float d0 = fmaf(x0, p.x, fmaf(y0, p.y, z0 * p.z));
        float d1 = fmaf(x1, p.x, fmaf(y1, p.y, z1 * p.z));
        float sq0 = fmaf(-2.0f, d0, pn0 + p.w);
        float sq1 = fmaf(-2.0f, d1, pn1 + p.w);
        if (mb + j == n0) sq0 = 1e30f;
        if (mb + j == n1) sq1 = 1e30f;
        mn0 = fminf(mn0, sq0);
        mn1 = fminf(mn1, sq1);
    }
    g_minsq[b][mc][n0] = mn0;
    g_minsq[b][mc][n1] = mn1;
}

// ---------------- K2: combine alpha -> invt ----------------
__global__ void k_alpha_comb() {
    int b = blockIdx.x, tid = threadIdx.x;
    __shared__ float red[256];
    float s = 0.0f;
    for (int n = tid; n < NN; n += 256) {
        float mn = 1e30f;
#pragma unroll
        for (int mc = 0; mc < 8; mc++) mn = fminf(mn, g_minsq[b][mc][n]);
        s += fsqrt_a(fmaxf(mn, FEPS));
    }
    red[tid] = s; __syncthreads();
    for (int st = 128; st > 0; st >>= 1) {
        if (tid < st) red[tid] += red[tid + st];
        __syncthreads();
    }
    if (tid == 0) {
        float alpha = red[0] * (1.0f / (float)NN);
        g_invt[b] = 1.0f / (4.0f * alpha);
    }
}

// ---------------- K3: column softmax denominators (partials) ----------------
// grid (4 mtile, 8 nchunk, 8 b), 256 threads; thread owns m0 and m0+256.
__global__ void k_colsum_part(const float* __restrict__ src, const float* __restrict__ tgt) {
    int b = blockIdx.z, mt = blockIdx.x, nc = blockIdx.y, tid = threadIdx.x;
    int m0 = mt * 512 + tid, m1 = m0 + 256;
    int nb = nc * 256;
    const float* S = src + b * 3 * NN;
    const float* T = tgt + b * 3 * MM;
    __shared__ float4 tile[256];
    {
        float a = S[nb + tid], c = S[NN + nb + tid], d = S[2 * NN + nb + tid];
        tile[tid] = make_float4(a, c, d, a * a + c * c + d * d);
    }
    float x0 = T[m0], y0 = T[MM + m0], z0 = T[2 * MM + m0];
    float x1 = T[m1], y1 = T[MM + m1], z1 = T[2 * MM + m1];
    float pn0 = x0 * x0 + y0 * y0 + z0 * z0;
    float pn1 = x1 * x1 + y1 * y1 + z1 * z1;
    float c1 = -g_invt[b] * L2E;
    __syncthreads();
    float s0 = 0.0f, s1 = 0.0f;
#pragma unroll 8
    for (int j = 0; j < 256; j++) {
        float4 p = tile[j];
        float d0 = fmaf(x0, p.x, fmaf(y0, p.y, z0 * p.z));
        float d1 = fmaf(x1, p.x, fmaf(y1, p.y, z1 * p.z));
        float sq0 = fmaf(-2.0f, d0, pn0 + p.w);
        float sq1 = fmaf(-2.0f, d1, pn1 + p.w);
        s0 += exp2f(fsqrt_a(fmaxf(sq0, FEPS)) * c1);
        s1 += exp2f(fsqrt_a(fmaxf(sq1, FEPS)) * c1);
    }
    g_colpart[b][nc][m0] = s0;
    g_colpart[b][nc][m1] = s1;
}

// ---------------- K4: main pass partials (invC combined inline) ----------------
// grid (4 ntile, 8 mchunk, 8 b), 256 threads; thread owns n0 and n0+256.
__global__ void k_main_part(const float* __restrict__ src, const float* __restrict__ tgt,
                            const int* __restrict__ iter) {
    int b = blockIdx.z, nt = blockIdx.x, mc = blockIdx.y, tid = threadIdx.x;
    int n0 = nt * 512 + tid, n1 = n0 + 256;
    int mb = mc * 256;
    const float* S = src + b * 3 * NN;
    const float* T = tgt + b * 3 * MM;
    __shared__ float4 tile[256];
    __shared__ float tic[256];
    {
        float a = T[mb + tid], c = T[MM + mb + tid], d = T[2 * MM + mb + tid];
        tile[tid] = make_float4(a, c, d, a * a + c * c + d * d);
        float cs = 0.0f;
#pragma unroll
        for (int nc = 0; nc < 8; nc++) cs += g_colpart[b][nc][mb + tid];
        tic[tid] = frcp_a(cs);
    }
    float x0 = S[n0], y0 = S[NN + n0], z0 = S[2 * NN + n0];
    float x1 = S[n1], y1 = S[NN + n1], z1 = S[2 * NN + n1];
    float pn0 = x0 * x0 + y0 * y0 + z0 * z0;
    float pn1 = x1 * x1 + y1 * y1 + z1 * z1;
    float c1 = -g_invt[b] * L2E;
    float invT = exp2f((float)(*iter - 1));      // 1/T = 2^(iter-1)
    float c2 = -invT * L2E;
    __syncthreads();
    float R0 = 0.f, S20 = 0.f, G0 = 0.f, a0 = 0.f, a1 = 0.f, a2 = 0.f;
    float R1 = 0.f, S21 = 0.f, G1 = 0.f, b0 = 0.f, b1 = 0.f, b2 = 0.f;
#pragma unroll 4
    for (int j = 0; j < 256; j++) {
        float4 p = tile[j];
        float ic = tic[j];
        float dt0 = fmaf(x0, p.x, fmaf(y0, p.y, z0 * p.z));
        float dt1 = fmaf(x1, p.x, fmaf(y1, p.y, z1 * p.z));
        float sq0 = fmaf(-2.0f, dt0, pn0 + p.w);
        float sq1 = fmaf(-2.0f, dt1, pn1 + p.w);
        float d0 = fsqrt_a(fmaxf(sq0, FEPS));
        float d1 = fsqrt_a(fmaxf(sq1, FEPS));
        float e0 = exp2f(d0 * c1), f0 = exp2f(d0 * c2);
        float e1 = exp2f(d1 * c1), f1 = exp2f(d1 * c2);
        float w0 = e0 * e0 * ic;
        float w1 = e1 * e1 * ic;
        R0 += e0;  S20 += w0;  G0 = fmaf(w0, f0, G0);
        a0 = fmaf(w0, p.x, a0); a1 = fmaf(w0, p.y, a1); a2 = fmaf(w0, p.z, a2);
        R1 += e1;  S21 += w1;  G1 = fmaf(w1, f1, G1);
        b0 = fmaf(w1, p.x, b0); b1 = fmaf(w1, p.y, b1); b2 = fmaf(w1, p.z, b2);
    }
    g_part6[b][mc][0][n0] = R0;  g_part6[b][mc][0][n1] = R1;
    g_part6[b][mc][1][n0] = S20; g_part6[b][mc][1][n1] = S21;
    g_part6[b][mc][2][n0] = G0;  g_part6[b][mc][2][n1] = G1;
    g_part6[b][mc][3][n0] = a0;  g_part6[b][mc][3][n1] = b0;
    g_part6[b][mc][4][n0] = a1;  g_part6[b][mc][4][n1] = b1;
    g_part6[b][mc][5][n0] = a2;  g_part6[b][mc][5][n1] = b2;
}

// ---------------- 3x3 Procrustes SVD (double, one thread) ----------------
__device__ void svd3_kabsch(const double H[3][3], double R[3][3]) {
    double A[3][3];
    for (int i = 0; i < 3; i++)
        for (int j = 0; j < 3; j++) {
            double s = 0;
            for (int k = 0; k < 3; k++) s += H[k][i] * H[k][j];
            A[i][j] = s;
        }
    double V[3][3] = {{1,0,0},{0,1,0},{0,0,1}};
    const int PQ[3][2] = {{0,1},{0,2},{1,2}};
    for (int sweep = 0; sweep < 30; sweep++) {
        double off = fabs(A[0][1]) + fabs(A[0][2]) + fabs(A[1][2]);
        if (off < 1e-30) break;
        for (int r = 0; r < 3; r++) {
            int p = PQ[r][0], q = PQ[r][1];
            double apq = A[p][q];
            if (fabs(apq) < 1e-300) continue;
            double theta = (A[q][q] - A[p][p]) / (2.0 * apq);
            double t = ((theta >= 0.0) ? 1.0 : -1.0) / (fabs(theta) + sqrt(1.0 + theta * theta));
            double c = 1.0 / sqrt(1.0 + t * t), s = t * c;
            for (int k = 0; k < 3; k++) {
                double akp = A[k][p], akq = A[k][q];
                A[k][p] = c * akp - s * akq;
                A[k][q] = s * akp + c * akq;
            }
            for (int k = 0; k < 3; k++) {
                double apk = A[p][k], aqk = A[q][k];
                A[p][k] = c * apk - s * aqk;
                A[q][k] = s * apk + c * aqk;
            }
            for (int k = 0; k < 3; k++) {
                double vkp = V[k][p], vkq = V[k][q];
                V[k][p] = c * vkp - s * vkq;
                V[k][q] = s * vkp + c * vkq;
            }
        }
    }
    int idx[3] = {0, 1, 2};
    double lam[3] = {A[0][0], A[1][1], A[2][2]};
    for (int i = 0; i < 2; i++)
        for (int j = i + 1; j < 3; j++)
            if (lam[idx[j]] > lam[idx[i]]) { int t = idx[i]; idx[i] = idx[j]; idx[j] = t; }
    double U[3][3], Vs[3][3];
    for (int i = 0; i < 3; i++) {
        int id = idx[i];
        double v0 = V[0][id], v1 = V[1][id], v2 = V[2][id];
        double u0 = H[0][0]*v0 + H[0][1]*v1 + H[0][2]*v2;
        double u1 = H[1][0]*v0 + H[1][1]*v1 + H[1][2]*v2;
        double u2 = H[2][0]*v0 + H[2][1]*v1 + H[2][2]*v2;
        double sig = sqrt(u0*u0 + u1*u1 + u2*u2);
        sig = (sig > 1e-300) ? sig : 1e-300;
        U[0][i] = u0 / sig; U[1][i] = u1 / sig; U[2][i] = u2 / sig;
        Vs[0][i] = v0; Vs[1][i] = v1; Vs[2][i] = v2;
    }
    double detH = H[0][0]*(H[1][1]*H[2][2] - H[1][2]*H[2][1])
                - H[0][1]*(H[1][0]*H[2][2] - H[1][2]*H[2][0])
                + H[0][2]*(H[1][0]*H[2][1] - H[1][1]*H[2][0]);
    double flip = (detH < 0.0) ? -1.0 : 1.0;
    Vs[0][2] *= flip; Vs[1][2] *= flip; Vs[2][2] *= flip;
    for (int r = 0; r < 3; r++)
        for (int c = 0; c < 3; c++)
            R[r][c] = Vs[r][0]*U[c][0] + Vs[r][1]*U[c][1] + Vs[r][2]*U[c][2];
}

// ---------------- K5: finalize (gamma, src_corr) + per-batch reduce + SVD ----------------
// out layout: [0,72) R, [72,96) t, [96, 96+B*3*N) src_corr
__global__ void k_reduce_svd(const float* __restrict__ src, float* __restrict__ out) {
    int b = blockIdx.x, tid = threadIdx.x;
    const float* S = src + b * 3 * NN;
    float* corr = out + 96 + b * 3 * NN;
    float acc[16];
#pragma unroll
    for (int k = 0; k < 16; k++) acc[k] = 0.0f;
    for (int n = tid; n < NN; n += 256) {
        float Rn = 0.f, S2 = 0.f, G = 0.f, c0 = 0.f, c1 = 0.f, c2 = 0.f;
#pragma unroll
        for (int mc = 0; mc < 8; mc++) {
            Rn += g_part6[b][mc][0][n];
            S2 += g_part6[b][mc][1][n];
            G  += g_part6[b][mc][2][n];
            c0 += g_part6[b][mc][3][n];
            c1 += g_part6[b][mc][4][n];
            c2 += g_part6[b][mc][5][n];
        }
        float g = G / Rn;                           // gamma
        float invden = 1.0f / (S2 + FEPS * Rn);     // scores_norm denom * Rn
        float cx = c0 * invden, cy = c1 * invden, cz = c2 * invden;
        corr[n]          = cx;
        corr[NN + n]     = cy;
        corr[2 * NN + n] = cz;
        float sx = S[n], sy = S[NN + n], sz = S[2 * NN + n];
        acc[0] += g;
        acc[1] += g * sx;  acc[2] += g * sy;  acc[3] += g * sz;
        acc[4] += g * cx;  acc[5] += g * cy;  acc[6] += g * cz;
        acc[7]  += g * sx * cx; acc[8]  += g * sx * cy; acc[9]  += g * sx * cz;
        acc[10] += g * sy * cx; acc[11] += g * sy * cy; acc[12] += g * sy * cz;
        acc[13] += g * sz * cx; acc[14] += g * sz * cy; acc[15] += g * sz * cz;
    }
    __shared__ float red[256];
    __shared__ float tot[16];
    for (int k = 0; k < 16; k++) {
        red[tid] = acc[k]; __syncthreads();
        for (int st = 128; st > 0; st >>= 1) {
            if (tid < st) red[tid] += red[tid + st];
            __syncthreads();
        }
        if (tid == 0) tot[k] = red[0];
        __syncthreads();
    }
    if (tid == 0) {
        double g1 = tot[0];
        double Ss[3] = {tot[1], tot[2], tot[3]};
        double Sc[3] = {tot[4], tot[5], tot[6]};
        double Mm[3][3] = {{tot[7], tot[8], tot[9]},
                           {tot[10], tot[11], tot[12]},
                           {tot[13], tot[14], tot[15]}};
        double gsum = g1 + 1e-12;
        double sm[3], cm[3];
        for (int d = 0; d < 3; d++) { sm[d] = Ss[d] / gsum; cm[d] = Sc[d] / gsum; }
        double H[3][3];
        for (int r = 0; r < 3; r++)
            for (int c = 0; c < 3; c++)
                H[r][c] = Mm[r][c] - sm[r] * Sc[c] - cm[c] * Ss[r] + sm[r] * cm[c] * g1;
        H[0][0] += 1e-12; H[1][1] += 2e-12; H[2][2] += 3e-12;
        double R[3][3];
        svd3_kabsch(H, R);
        for (int r = 0; r < 3; r++)
            for (int c = 0; c < 3; c++)
                out[b * 9 + r * 3 + c] = (float)R[r][c];
        for (int d = 0; d < 3; d++)
            out[72 + b * 3 + d] =
                (float)(-(R[d][0] * sm[0] + R[d][1] * sm[1] + R[d][2] * sm[2]) + cm[d]);
    }
}

// ---------------- launch ----------------
extern "C" void kernel_launch(void* const* d_in, const int* in_sizes, int n_in,
                              void* d_out, int out_size) {
    const float* src = (const float*)d_in[0];
    const float* tgt = (const float*)d_in[1];
    const int* iter = (const int*)d_in[2];
    float* out = (float*)d_out;

    k_alpha_part<<<dim3(4, 8, 8), 256>>>(src);
    k_alpha_comb<<<8, 256>>>();
    k_colsum_part<<<dim3(4, 8, 8), 256>>>(src, tgt);
    k_main_part<<<dim3(4, 8, 8), 256>>>(src, tgt, iter);
    k_reduce_svd<<<8, 256>>>(src, out);
}